// round 8
// baseline (speedup 1.0000x reference)
#include <cuda_runtime.h>
#include <cuda_fp16.h>
#include <cstdint>

#define BN_EPS 1e-5f

// ---------------- scratch ----------------
__device__ __half g_y1h[4 * 64 * 64 * 128];
__device__ __half g_y4h[4 * 64 * 64 * 128];
__device__ __half g_y5h[4 * 64 * 64 * 128];
__device__ __half g_xk[4 * 64 * 64 * 1024];
__device__ __half g_xn[4 * 64 * 64 * 1024];
__device__ __half g_U[2 * 16 * 128 * 1024];      // winograd weights
__device__ __half g_V[2ull * 16 * 4096 * 1024];  // winograd inputs (256MB)
__device__ __half g_M[2ull * 16 * 4096 * 128];   // winograd products (32MB)
__device__ __half g_w5[128 * 1152];
__device__ __half g_o0[4 * 64 * 64 * 128];
__device__ float g_part[2 * 2048 * 2 * 128];     // wino_out BN partials
__device__ float g_part5[64 * 2 * 128];
__device__ float g_ppool[4 * 16 * 128];
__device__ float g_scale[3][128];
__device__ float g_shift[3][128];

// ---------------- helpers ----------------
__device__ __forceinline__ uint32_t smem_u32(const void* p) {
    uint32_t a;
    asm("{ .reg .u64 t; cvta.to.shared.u64 t, %1; cvt.u32.u64 %0, t; }" : "=r"(a) : "l"(p));
    return a;
}
__device__ __forceinline__ void cp16(uint32_t dst, const void* src, int sz) {
    asm volatile("cp.async.cg.shared.global [%0], [%1], 16, %2;\n" :: "r"(dst), "l"(src), "r"(sz));
}
#define CPC() asm volatile("cp.async.commit_group;" ::: "memory")
__device__ __forceinline__ void ldsm_x4(uint32_t& r0, uint32_t& r1, uint32_t& r2,
                                        uint32_t& r3, uint32_t addr) {
    asm volatile("ldmatrix.sync.aligned.m8n8.x4.shared.b16 {%0,%1,%2,%3}, [%4];"
                 : "=r"(r0), "=r"(r1), "=r"(r2), "=r"(r3) : "r"(addr));
}
__device__ __forceinline__ void mma16816(float* d, const uint32_t* a, const uint32_t* b) {
    asm volatile(
        "mma.sync.aligned.m16n8k16.row.col.f32.f16.f16.f32 "
        "{%0,%1,%2,%3}, {%4,%5,%6,%7}, {%8,%9}, {%0,%1,%2,%3};"
        : "+f"(d[0]), "+f"(d[1]), "+f"(d[2]), "+f"(d[3])
        : "r"(a[0]), "r"(a[1]), "r"(a[2]), "r"(a[3]), "r"(b[0]), "r"(b[1]));
}

// ---------------- winograd weight transform: U = G w G^T ----------------
__global__ void wino_w_kernel(const float* __restrict__ w, __half* __restrict__ U)
{
    int c = blockIdx.x;
    for (int ci = threadIdx.x; ci < 1024; ci += 256) {
        const float* wp = w + (size_t)(c * 1024 + ci) * 9;
        float a[3][3];
#pragma unroll
        for (int i = 0; i < 3; i++)
#pragma unroll
            for (int j = 0; j < 3; j++) a[i][j] = wp[i * 3 + j];
        float t[4][3];
#pragma unroll
        for (int j = 0; j < 3; j++) {
            t[0][j] = a[0][j];
            t[1][j] = 0.5f * (a[0][j] + a[1][j] + a[2][j]);
            t[2][j] = 0.5f * (a[0][j] - a[1][j] + a[2][j]);
            t[3][j] = a[2][j];
        }
#pragma unroll
        for (int i = 0; i < 4; i++) {
            float u0 = t[i][0];
            float u1 = 0.5f * (t[i][0] + t[i][1] + t[i][2]);
            float u2 = 0.5f * (t[i][0] - t[i][1] + t[i][2]);
            float u3 = t[i][2];
            size_t base = (size_t)c * 1024 + ci;
            U[(size_t)(i * 4 + 0) * 131072 + base] = __float2half_rn(u0);
            U[(size_t)(i * 4 + 1) * 131072 + base] = __float2half_rn(u1);
            U[(size_t)(i * 4 + 2) * 131072 + base] = __float2half_rn(u2);
            U[(size_t)(i * 4 + 3) * 131072 + base] = __float2half_rn(u3);
        }
    }
}

// ---------------- input transform: V[m][tile][ch] = B^T d B ----------------
__global__ __launch_bounds__(256) void wino_in_kernel(
    const __half* __restrict__ x0, const __half* __restrict__ x1,
    __half* __restrict__ V)
{
    int tile = blockIdx.x;
    int sel = blockIdx.y;
    const __half* x = sel ? x1 : x0;
    int b = tile >> 10, tr = (tile >> 5) & 31, tc = tile & 31;
    int ch0 = threadIdx.x * 4;

    __half2 d[4][4][2];
#pragma unroll
    for (int r = 0; r < 4; r++) {
        int gr = 2 * tr - 1 + r;
#pragma unroll
        for (int cl = 0; cl < 4; cl++) {
            int gc = 2 * tc - 1 + cl;
            if ((unsigned)gr < 64u && (unsigned)gc < 64u) {
                uint2 v = *(const uint2*)(x + ((size_t)((b * 64 + gr) * 64 + gc)) * 1024 + ch0);
                d[r][cl][0] = *(__half2*)&v.x;
                d[r][cl][1] = *(__half2*)&v.y;
            } else {
                d[r][cl][0] = __half2half2(__float2half(0.f));
                d[r][cl][1] = d[r][cl][0];
            }
        }
    }
    __half* Vb = V + ((size_t)(sel * 16) * 4096) * 1024;
#pragma unroll
    for (int hl = 0; hl < 2; hl++) {
        __half2 t[4][4];
#pragma unroll
        for (int cl = 0; cl < 4; cl++) {
            t[0][cl] = __hsub2(d[0][cl][hl], d[2][cl][hl]);
            t[1][cl] = __hadd2(d[1][cl][hl], d[2][cl][hl]);
            t[2][cl] = __hsub2(d[2][cl][hl], d[1][cl][hl]);
            t[3][cl] = __hsub2(d[1][cl][hl], d[3][cl][hl]);
        }
#pragma unroll
        for (int i = 0; i < 4; i++) {
            __half2 v0 = __hsub2(t[i][0], t[i][2]);
            __half2 v1 = __hadd2(t[i][1], t[i][2]);
            __half2 v2 = __hsub2(t[i][2], t[i][1]);
            __half2 v3 = __hsub2(t[i][1], t[i][3]);
            size_t base = (size_t)tile * 1024 + ch0 + hl * 2;
            *(__half2*)(Vb + (size_t)(i * 4 + 0) * 4194304 + base) = v0;
            *(__half2*)(Vb + (size_t)(i * 4 + 1) * 4194304 + base) = v1;
            *(__half2*)(Vb + (size_t)(i * 4 + 2) * 4194304 + base) = v2;
            *(__half2*)(Vb + (size_t)(i * 4 + 3) * 4194304 + base) = v3;
        }
    }
}

// ---------------- batched GEMM: M[m] = U[m] @ V[m]^T ----------------
// CTA: 128 c_out x 256 tiles; K=1024 in chunks of 32; 8 warps 2(M)x4(N).
#define PITCH 80
#define STG_B 10240
#define STAGE_SZ 30720

__global__ __launch_bounds__(256, 1) void wino_gemm_kernel(
    const __half* __restrict__ Vg, const __half* __restrict__ Ug,
    __half* __restrict__ Mg)
{
    extern __shared__ char smem[];
    const uint32_t sbase = smem_u32(smem);
    const int tid = threadIdx.x;
    const int wid = tid >> 5, lane = tid & 31;
    const int n0 = blockIdx.x * 256;
    const int mm = blockIdx.z * 16 + blockIdx.y;

    const __half* Vm = Vg + (size_t)mm * 4194304;
    const __half* Um = Ug + (size_t)mm * 131072;
    __half* Mm = Mg + (size_t)mm * 524288;

    const int mi = wid & 1, ni = wid >> 1;
    const int m0 = mi * 64;
    const int tig = lane & 3, gid = lane >> 2;
    const uint32_t frag_off = (uint32_t)((lane & 15) * PITCH + (lane >> 4) * 16);
    const int n0w = ni * 64;

    float acc[4][8][4];
#pragma unroll
    for (int a = 0; a < 4; a++)
#pragma unroll
        for (int j = 0; j < 8; j++)
#pragma unroll
            for (int e = 0; e < 4; e++) acc[a][j][e] = 0.f;

    auto load = [&](uint32_t sb, int i) {
        int k0 = i * 32;
#pragma unroll
        for (int u = 0; u < 2; u++) {
            int idx = tid * 2 + u;
            int row = idx >> 2, c16 = idx & 3;
            cp16(sb + row * PITCH + c16 * 16, Um + row * 1024 + k0 + c16 * 8, 16);
        }
#pragma unroll
        for (int u = 0; u < 4; u++) {
            int idx = tid * 4 + u;
            int px = idx >> 2, c16 = idx & 3;
            cp16(sb + STG_B + px * PITCH + c16 * 16,
                 Vm + (size_t)(n0 + px) * 1024 + k0 + c16 * 8, 16);
        }
    };

    load(sbase, 0); CPC();
    load(sbase + STAGE_SZ, 1); CPC();

    for (int i = 0; i < 32; i++) {
        uint32_t st = (i & 1) ? sbase + STAGE_SZ : sbase;
        if (i + 1 < 32) asm volatile("cp.async.wait_group 1;" ::: "memory");
        else            asm volatile("cp.async.wait_group 0;" ::: "memory");
        __syncthreads();
#pragma unroll
        for (int s = 0; s < 2; s++) {
            uint32_t ah[4][4], bf[4][4];
#pragma unroll
            for (int tt = 0; tt < 4; tt++)
                ldsm_x4(ah[tt][0], ah[tt][1], ah[tt][2], ah[tt][3],
                        st + (m0 + tt * 16) * PITCH + s * 32 + frag_off);
#pragma unroll
            for (int q = 0; q < 4; q++)
                ldsm_x4(bf[q][0], bf[q][1], bf[q][2], bf[q][3],
                        st + STG_B + (n0w + q * 16) * PITCH + s * 32 + frag_off);
#pragma unroll
            for (int tt = 0; tt < 4; tt++)
#pragma unroll
                for (int q = 0; q < 4; q++) {
                    uint32_t b0[2] = { bf[q][0], bf[q][2] };
                    uint32_t b1[2] = { bf[q][1], bf[q][3] };
                    mma16816(acc[tt][q * 2 + 0], ah[tt], b0);
                    mma16816(acc[tt][q * 2 + 1], ah[tt], b1);
                }
        }
        __syncthreads();
        if (i + 2 < 32) { load(st, i + 2); CPC(); }
    }
    __syncthreads();

    // transpose-store to M[tile][c]
    __half* sy = (__half*)smem;   // [128][136]
#pragma unroll
    for (int pass = 0; pass < 2; pass++) {
        __syncthreads();
        if ((ni >> 1) == pass) {
            int pxb = (ni & 1) * 64;
            int c0 = m0 + gid;
#pragma unroll
            for (int tt = 0; tt < 4; tt++) {
                int cc = c0 + tt * 16;
#pragma unroll
                for (int j = 0; j < 8; j++) {
                    int px = pxb + j * 8 + tig * 2;
                    sy[px * 136 + cc]           = __float2half_rn(acc[tt][j][0]);
                    sy[(px + 1) * 136 + cc]     = __float2half_rn(acc[tt][j][1]);
                    sy[px * 136 + cc + 8]       = __float2half_rn(acc[tt][j][2]);
                    sy[(px + 1) * 136 + cc + 8] = __float2half_rn(acc[tt][j][3]);
                }
            }
        }
        __syncthreads();
        int px = tid >> 1, hp = tid & 1;
        uint4* dst = (uint4*)(Mm + (size_t)(n0 + pass * 128 + px) * 128 + hp * 64);
        const uint4* src = (const uint4*)(sy + px * 136 + hp * 64);
#pragma unroll
        for (int k = 0; k < 8; k++) dst[k] = src[k];
    }
}

// ---------------- output transform: y = A^T M A + BN partials ----------------
__global__ __launch_bounds__(256) void wino_out_kernel(
    const __half* __restrict__ Mg, __half* __restrict__ y0,
    __half* __restrict__ y1p, float* __restrict__ part)
{
    int sel = blockIdx.y;
    __half* yh = sel ? y1p : y0;
    const __half* Mb = Mg + (size_t)(sel * 16) * 524288;
    int tl = threadIdx.x >> 7;               // 0..1
    int c = threadIdx.x & 127;
    int tile = blockIdx.x * 2 + tl;
    int b = tile >> 10, tr = (tile >> 5) & 31, tc = tile & 31;

    float Mv[16];
#pragma unroll
    for (int i = 0; i < 16; i++)
        Mv[i] = __half2float(Mb[(size_t)i * 524288 + (size_t)tile * 128 + c]);

    float p0[4], p1[4];
#pragma unroll
    for (int j = 0; j < 4; j++) {
        p0[j] = Mv[0 * 4 + j] + Mv[1 * 4 + j] + Mv[2 * 4 + j];
        p1[j] = Mv[1 * 4 + j] - Mv[2 * 4 + j] - Mv[3 * 4 + j];
    }
    float y00 = p0[0] + p0[1] + p0[2];
    float y01 = p0[1] - p0[2] - p0[3];
    float y10 = p1[0] + p1[1] + p1[2];
    float y11 = p1[1] - p1[2] - p1[3];

    size_t base = ((size_t)((b * 64 + 2 * tr) * 64 + 2 * tc)) * 128 + c;
    yh[base]              = __float2half_rn(y00);
    yh[base + 128]        = __float2half_rn(y01);
    yh[base + 64 * 128]   = __float2half_rn(y10);
    yh[base + 65 * 128]   = __float2half_rn(y11);

    __shared__ float sh[256], sq[256];
    sh[threadIdx.x] = y00 + y01 + y10 + y11;
    sq[threadIdx.x] = y00 * y00 + y01 * y01 + y10 * y10 + y11 * y11;
    __syncthreads();
    if (threadIdx.x < 128) {
        float* pb = part + (size_t)sel * 2048 * 256;
        pb[(blockIdx.x * 2 + 0) * 128 + c] = sh[c] + sh[c + 128];
        pb[(blockIdx.x * 2 + 1) * 128 + c] = sq[c] + sq[c + 128];
    }
}

// ---------------- direct conv (conv5) ----------------
template <int CIN>
__global__ __launch_bounds__(256, 1) void conv_mma_kernel(
    const __half* __restrict__ x, const __half* __restrict__ w,
    __half* __restrict__ yh, float* __restrict__ part)
{
    extern __shared__ char smem[];
    const uint32_t sbase = smem_u32(smem);
    const int tid = threadIdx.x;
    const int wid = tid >> 5, lane = tid & 31;
    int b = blockIdx.x >> 4;
    int h0 = (blockIdx.x & 15) * 4;
    const int mi = wid & 1, ni = wid >> 1;
    const int m0 = mi * 64;
    const int tig = lane & 3, gid = lane >> 2;
    const uint32_t frag_off = (uint32_t)((lane & 15) * PITCH + (lane >> 4) * 16);
    const int n0 = ni * 64;
    const int K = CIN * 9;

    float acc[4][8][4];
#pragma unroll
    for (int a = 0; a < 4; a++)
#pragma unroll
        for (int j = 0; j < 8; j++)
#pragma unroll
            for (int e = 0; e < 4; e++) acc[a][j][e] = 0.f;

    auto load = [&](uint32_t sb, int iter) {
        int pos = iter % 9, cic = iter / 9;
        int kh = pos / 3, kw = pos - 3 * kh;
        int k0 = pos * CIN + cic * 32;
#pragma unroll
        for (int u = 0; u < 2; u++) {
            int idx = tid * 2 + u;
            int row = idx >> 2, c16 = idx & 3;
            cp16(sb + row * PITCH + c16 * 16, w + row * K + k0 + c16 * 8, 16);
        }
#pragma unroll
        for (int u = 0; u < 4; u++) {
            int idx = tid * 4 + u;
            int px = idx >> 2, c16 = idx & 3;
            int r = px >> 6, ww = px & 63;
            int y = h0 + r + kh - 1, xw = ww + kw - 1;
            bool ok = ((unsigned)y < 64u) && ((unsigned)xw < 64u);
            const __half* src = x +
                ((size_t)((b * 64 + (ok ? y : 0)) * 64 + (ok ? xw : 0))) * CIN +
                cic * 32 + c16 * 8;
            cp16(sb + STG_B + px * PITCH + c16 * 16, src, ok ? 16 : 0);
        }
    };

    constexpr int NIT = 9 * (CIN / 32);
    load(sbase, 0); CPC();
    load(sbase + STAGE_SZ, 1); CPC();

    for (int i = 0; i < NIT; i++) {
        uint32_t st = (i & 1) ? sbase + STAGE_SZ : sbase;
        if (i + 1 < NIT) asm volatile("cp.async.wait_group 1;" ::: "memory");
        else             asm volatile("cp.async.wait_group 0;" ::: "memory");
        __syncthreads();
#pragma unroll
        for (int s = 0; s < 2; s++) {
            uint32_t ah[4][4], bf[4][4];
#pragma unroll
            for (int tt = 0; tt < 4; tt++)
                ldsm_x4(ah[tt][0], ah[tt][1], ah[tt][2], ah[tt][3],
                        st + (m0 + tt * 16) * PITCH + s * 32 + frag_off);
#pragma unroll
            for (int q = 0; q < 4; q++)
                ldsm_x4(bf[q][0], bf[q][1], bf[q][2], bf[q][3],
                        st + STG_B + (n0 + q * 16) * PITCH + s * 32 + frag_off);
#pragma unroll
            for (int tt = 0; tt < 4; tt++)
#pragma unroll
                for (int q = 0; q < 4; q++) {
                    uint32_t b0[2] = { bf[q][0], bf[q][2] };
                    uint32_t b1[2] = { bf[q][1], bf[q][3] };
                    mma16816(acc[tt][q * 2 + 0], ah[tt], b0);
                    mma16816(acc[tt][q * 2 + 1], ah[tt], b1);
                }
        }
        __syncthreads();
        if (i + 2 < NIT) { load(st, i + 2); CPC(); }
    }
    __syncthreads();

    // BN partials
    float* sst = (float*)smem;
    float* ssq = (float*)(smem + 2048);
#pragma unroll
    for (int tt = 0; tt < 4; tt++) {
        float a0 = 0.f, q0 = 0.f, a1 = 0.f, q1 = 0.f;
#pragma unroll
        for (int j = 0; j < 8; j++) {
            float x0 = acc[tt][j][0], x1 = acc[tt][j][1];
            float x2 = acc[tt][j][2], x3 = acc[tt][j][3];
            a0 += x0 + x1; q0 += x0 * x0 + x1 * x1;
            a1 += x2 + x3; q1 += x2 * x2 + x3 * x3;
        }
#pragma unroll
        for (int d = 1; d < 4; d <<= 1) {
            a0 += __shfl_xor_sync(0xffffffff, a0, d);
            q0 += __shfl_xor_sync(0xffffffff, q0, d);
            a1 += __shfl_xor_sync(0xffffffff, a1, d);
            q1 += __shfl_xor_sync(0xffffffff, q1, d);
        }
        if (tig == 0) {
            int lc = tt * 16 + gid;
            sst[wid * 64 + lc] = a0;     ssq[wid * 64 + lc] = q0;
            sst[wid * 64 + lc + 8] = a1; ssq[wid * 64 + lc + 8] = q1;
        }
    }
    __syncthreads();
    if (tid < 128) {
        int c = tid, mi2 = c >> 6, lc = c & 63;
        float s = 0.f, q = 0.f;
#pragma unroll
        for (int k = 0; k < 4; k++) {
            s += sst[(2 * k + mi2) * 64 + lc];
            q += ssq[(2 * k + mi2) * 64 + lc];
        }
        part[(blockIdx.x * 2 + 0) * 128 + c] = s;
        part[(blockIdx.x * 2 + 1) * 128 + c] = q;
    }

    // NHWC fp16 store
    __half* sy = (__half*)(smem + 8192);
#pragma unroll
    for (int pass = 0; pass < 2; pass++) {
        __syncthreads();
        if ((ni >> 1) == pass) {
            int pxb = (ni & 1) * 64;
            int c0 = m0 + gid;
#pragma unroll
            for (int tt = 0; tt < 4; tt++) {
                int cc = c0 + tt * 16;
#pragma unroll
                for (int j = 0; j < 8; j++) {
                    int px = pxb + j * 8 + tig * 2;
                    sy[px * 136 + cc]           = __float2half_rn(acc[tt][j][0]);
                    sy[(px + 1) * 136 + cc]     = __float2half_rn(acc[tt][j][1]);
                    sy[px * 136 + cc + 8]       = __float2half_rn(acc[tt][j][2]);
                    sy[(px + 1) * 136 + cc + 8] = __float2half_rn(acc[tt][j][3]);
                }
            }
        }
        __syncthreads();
        int px = tid >> 1, hp = tid & 1;
        int hrow = h0 + pass * 2 + (px >> 6);
        int wcol = px & 63;
        uint4* dst = (uint4*)(yh + ((size_t)((b * 64 + hrow) * 64 + wcol)) * 128 + hp * 64);
        const uint4* src = (const uint4*)(sy + px * 136 + hp * 64);
#pragma unroll
        for (int k = 0; k < 8; k++) dst[k] = src[k];
    }
}

// ---------------- prep / BN / elementwise (unchanged from R6) ----------------
__global__ void prep_w_kernel(const float* __restrict__ w,
                              __half* __restrict__ wo, int CIN)
{
    int K = CIN * 9;
    int total = 128 * K;
    for (int i = blockIdx.x * blockDim.x + threadIdx.x; i < total;
         i += gridDim.x * blockDim.x) {
        int c = i / K, k = i - c * K;
        int pos = k / CIN, ci = k - pos * CIN;
        wo[i] = __float2half_rn(w[(c * CIN + ci) * 9 + pos]);
    }
}

__global__ void prep_x_kernel(const float* __restrict__ x, __half* __restrict__ xh)
{
    __shared__ float ttile[64][33];
    int bh = blockIdx.z;
    int b = bh >> 6, h = bh & 63;
    int ciT = blockIdx.y * 64, wT = blockIdx.x * 32;
    int tx = threadIdx.x, ty = threadIdx.y;
    int tid = ty * 32 + tx;
#pragma unroll
    for (int r = 0; r < 8; r++) {
        int cl = ty + r * 8;
        ttile[cl][tx] = x[((size_t)(b * 1024 + ciT + cl) * 64 + h) * 64 + wT + tx];
    }
    __syncthreads();
#pragma unroll
    for (int u = 0; u < 4; u++) {
        int idx = u * 256 + tid;
        int wloc = idx >> 5, cp = idx & 31;
        __half2 v = __floats2half2_rn(ttile[cp * 2][wloc], ttile[cp * 2 + 1][wloc]);
        size_t o2 = (((size_t)(b * 64 + h) * 64 + wT + wloc) * 1024 + ciT + cp * 2) >> 1;
        ((__half2*)xh)[o2] = v;
    }
}

__global__ void bn_reduce_kernel(const float* __restrict__ part, int nparts,
                                 const float* __restrict__ gamma,
                                 const float* __restrict__ beta,
                                 float* __restrict__ scale,
                                 float* __restrict__ shift)
{
    int c = threadIdx.x;
    float s = 0.f, q = 0.f;
    for (int i = 0; i < nparts; i++) {
        s += part[(i * 2 + 0) * 128 + c];
        q += part[(i * 2 + 1) * 128 + c];
    }
    float mean = s * (1.f / 16384.f);
    float var  = q * (1.f / 16384.f) - mean * mean;
    float sc = gamma[c] * rsqrtf(var + BN_EPS);
    scale[c] = sc;
    shift[c] = beta[c] - mean * sc;
}

__global__ __launch_bounds__(128) void local_weight_kernel(
    const float* __restrict__ atten,
    const __half* __restrict__ y1h,
    const float* __restrict__ sc1, const float* __restrict__ sf1,
    const __half* __restrict__ y4h,
    const float* __restrict__ sc4, const float* __restrict__ sf4,
    __half* __restrict__ o0)
{
    int bp0 = blockIdx.x * 2;
    __shared__ float att[2][81];
    for (int i = threadIdx.x; i < 162; i += 128)
        att[i / 81][i - (i / 81) * 81] = atten[(size_t)bp0 * 81 + i];
    __syncthreads();

    int px = threadIdx.x >> 6;
    int c2 = threadIdx.x & 63;
    int bp = bp0 + px;
    int b = bp >> 12, p = bp & 4095;
    int h = p >> 6, w = p & 63;

    float s1x = sc1[2 * c2], s1y = sc1[2 * c2 + 1];
    float f1x = sf1[2 * c2], f1y = sf1[2 * c2 + 1];

    float2 acc = make_float2(0.f, 0.f);
#pragma unroll
    for (int dh = 0; dh < 9; dh++) {
        int yy = h + dh - 4;
        if ((unsigned)yy >= 64u) continue;
        const __half2* row = (const __half2*)(y1h + (size_t)((b * 64 + yy) * 64) * 128) + c2;
#pragma unroll
        for (int dw = 0; dw < 9; dw++) {
            int xx = w + dw - 4;
            if ((unsigned)xx < 64u) {
                float2 v = __half22float2(row[(size_t)xx * 64]);
                float vx = fmaxf(fmaf(v.x, s1x, f1x), 0.f);
                float vy = fmaxf(fmaf(v.y, s1y, f1y), 0.f);
                float a = att[px][dh * 9 + dw];
                acc.x = fmaf(a, vx, acc.x);
                acc.y = fmaf(a, vy, acc.y);
            }
        }
    }
    float2 u = __half22float2(((const __half2*)(y4h + (size_t)bp * 128))[c2]);
    float lx = fmaxf(fmaf(u.x, sc4[2 * c2], sf4[2 * c2]), 0.f);
    float ly = fmaxf(fmaf(u.y, sc4[2 * c2 + 1], sf4[2 * c2 + 1]), 0.f);
    ((__half2*)(o0 + (size_t)bp * 128))[c2] = __floats2half2_rn(acc.x - lx, acc.y - ly);
}

__global__ void pool_part_kernel(const __half* __restrict__ y5h,
                                 const float* __restrict__ sc5,
                                 const float* __restrict__ sf5,
                                 float* __restrict__ ppool)
{
    int b = blockIdx.y, chunk = blockIdx.x;
    int t = threadIdx.x;
    int c = t & 127, pp = t >> 7;
    float sc = sc5[c], sf = sf5[c];
    const __half* base = y5h + ((size_t)(b * 4096 + chunk * 256)) * 128;
    float s = 0.f;
    for (int px = pp; px < 256; px += 2) {
        float v = __half2float(base[(size_t)px * 128 + c]);
        s += fmaxf(fmaf(v, sc, sf), 0.f);
    }
    __shared__ float sh[256];
    sh[t] = s;
    __syncthreads();
    if (t < 128) ppool[(size_t)(b * 16 + chunk) * 128 + c] = sh[t] + sh[t + 128];
}

__global__ void final_kernel(const float* __restrict__ ppool,
                             const float* __restrict__ fc1w,
                             const float* __restrict__ fc1b,
                             const float* __restrict__ fc2w,
                             const float* __restrict__ fc2b,
                             float* __restrict__ out)
{
    __shared__ float pooled[4][128];
    __shared__ float hbuf[4][10];
    int t = threadIdx.x;
    for (int b = 0; b < 4; b++) {
        float s = 0.f;
        for (int i = 0; i < 16; i++) s += ppool[(size_t)(b * 16 + i) * 128 + t];
        pooled[b][t] = s * (1.f / 4096.f);
    }
    __syncthreads();
    if (t < 40) {
        int b = t / 10, j = t % 10;
        float s = fc1b[j];
        const float* wr = fc1w + j * 128;
        for (int c = 0; c < 128; c++) s = fmaf(wr[c], pooled[b][c], s);
        hbuf[b][j] = s;
    }
    __syncthreads();
    if (t < 4) {
        float s = fc2b[0];
        for (int j = 0; j < 10; j++) s = fmaf(fc2w[j], hbuf[t][j], s);
        out[t] = s;
    }
}

// ---------------- launch ----------------
extern "C" void kernel_launch(void* const* d_in, const int* in_sizes, int n_in,
                              void* d_out, int out_size)
{
    const float* low_key    = (const float*)d_in[0];
    const float* low_nonkey = (const float*)d_in[1];
    const float* atten      = (const float*)d_in[2];
    const float* w1 = (const float*)d_in[3];
    const float* g1 = (const float*)d_in[4];
    const float* b1 = (const float*)d_in[5];
    const float* w4 = (const float*)d_in[6];
    const float* g4 = (const float*)d_in[7];
    const float* b4 = (const float*)d_in[8];
    const float* w5 = (const float*)d_in[9];
    const float* g5 = (const float*)d_in[10];
    const float* b5 = (const float*)d_in[11];
    const float* fc1w = (const float*)d_in[12];
    const float* fc1b = (const float*)d_in[13];
    const float* fc2w = (const float*)d_in[14];
    const float* fc2b = (const float*)d_in[15];
    float* out = (float*)d_out;

    __half *y1h, *y4h, *y5h, *xk, *xn, *U, *V, *M, *pw5, *o0;
    float *part, *part5, *ppool, *scale, *shift;
    cudaGetSymbolAddress((void**)&y1h, g_y1h);
    cudaGetSymbolAddress((void**)&y4h, g_y4h);
    cudaGetSymbolAddress((void**)&y5h, g_y5h);
    cudaGetSymbolAddress((void**)&xk, g_xk);
    cudaGetSymbolAddress((void**)&xn, g_xn);
    cudaGetSymbolAddress((void**)&U, g_U);
    cudaGetSymbolAddress((void**)&V, g_V);
    cudaGetSymbolAddress((void**)&M, g_M);
    cudaGetSymbolAddress((void**)&pw5, g_w5);
    cudaGetSymbolAddress((void**)&o0, g_o0);
    cudaGetSymbolAddress((void**)&part, g_part);
    cudaGetSymbolAddress((void**)&part5, g_part5);
    cudaGetSymbolAddress((void**)&ppool, g_ppool);
    cudaGetSymbolAddress((void**)&scale, g_scale);
    cudaGetSymbolAddress((void**)&shift, g_shift);

    float* scale1 = scale + 0 * 128; float* shift1 = shift + 0 * 128;
    float* scale4 = scale + 1 * 128; float* shift4 = shift + 1 * 128;
    float* scale5 = scale + 2 * 128; float* shift5 = shift + 2 * 128;

    const int CONV_SMEM = 2 * STAGE_SZ;  // 61440
    cudaFuncSetAttribute(wino_gemm_kernel,
                         cudaFuncAttributeMaxDynamicSharedMemorySize, CONV_SMEM);
    cudaFuncSetAttribute(conv_mma_kernel<128>,
                         cudaFuncAttributeMaxDynamicSharedMemorySize, CONV_SMEM);

    // prep
    wino_w_kernel<<<128, 256>>>(w1, U);
    wino_w_kernel<<<128, 256>>>(w4, U + (size_t)16 * 131072);
    prep_w_kernel<<<64, 256>>>(w5, pw5, 128);
    {
        dim3 g(2, 16, 256), blk(32, 8);
        prep_x_kernel<<<g, blk>>>(low_key, xk);
        prep_x_kernel<<<g, blk>>>(low_nonkey, xn);
    }

    // winograd conv1+conv4
    {
        dim3 gi(4096, 2);
        wino_in_kernel<<<gi, 256>>>(xk, xn, V);
        dim3 gg(16, 16, 2);
        wino_gemm_kernel<<<gg, 256, CONV_SMEM>>>(V, U, M);
        dim3 go(2048, 2);
        wino_out_kernel<<<go, 256>>>(M, y1h, y4h, part);
    }
    bn_reduce_kernel<<<1, 128>>>(part, 2048, g1, b1, scale1, shift1);
    bn_reduce_kernel<<<1, 128>>>(part + (size_t)2048 * 256, 2048, g4, b4, scale4, shift4);

    local_weight_kernel<<<8192, 128>>>(atten, y1h, scale1, shift1,
                                       y4h, scale4, shift4, o0);

    conv_mma_kernel<128><<<64, 256, CONV_SMEM>>>(o0, pw5, y5h, part5);
    bn_reduce_kernel<<<1, 128>>>(part5, 64, g5, b5, scale5, shift5);

    {
        dim3 g(16, 4);
        pool_part_kernel<<<g, 256>>>(y5h, scale5, shift5, ppool);
    }
    final_kernel<<<1, 128>>>(ppool, fc1w, fc1b, fc2w, fc2b, out);
}

// round 9
// speedup vs baseline: 1.7410x; 1.7410x over previous
#include <cuda_runtime.h>
#include <cuda_fp16.h>
#include <cstdint>

#define BN_EPS 1e-5f

// ---------------- scratch ----------------
__device__ __half g_y1h[4 * 64 * 64 * 128];
__device__ __half g_y4h[4 * 64 * 64 * 128];
__device__ __half g_y5h[4 * 64 * 64 * 128];
__device__ __half g_xk[4 * 64 * 64 * 1024];
__device__ __half g_xn[4 * 64 * 64 * 1024];
__device__ __half g_w1[128 * 9216];
__device__ __half g_w4[128 * 9216];
__device__ __half g_w5[128 * 1152];
__device__ __half g_o0[4 * 64 * 64 * 128];
__device__ float g_part[256 * 2 * 128];
__device__ float g_part5[128 * 2 * 128];
__device__ float g_ppool[4 * 16 * 128];
__device__ float g_scale[3][128];
__device__ float g_shift[3][128];

// ---------------- helpers ----------------
__device__ __forceinline__ uint32_t smem_u32(const void* p) {
    uint32_t a;
    asm("{ .reg .u64 t; cvta.to.shared.u64 t, %1; cvt.u32.u64 %0, t; }" : "=r"(a) : "l"(p));
    return a;
}
__device__ __forceinline__ void cp16(uint32_t dst, const void* src, int sz) {
    asm volatile("cp.async.cg.shared.global [%0], [%1], 16, %2;\n" :: "r"(dst), "l"(src), "r"(sz));
}
#define CPC() asm volatile("cp.async.commit_group;" ::: "memory")
__device__ __forceinline__ void ldsm_x4(uint32_t& r0, uint32_t& r1, uint32_t& r2,
                                        uint32_t& r3, uint32_t addr) {
    asm volatile("ldmatrix.sync.aligned.m8n8.x4.shared.b16 {%0,%1,%2,%3}, [%4];"
                 : "=r"(r0), "=r"(r1), "=r"(r2), "=r"(r3) : "r"(addr));
}
__device__ __forceinline__ void mma16816(float* d, const uint32_t* a, const uint32_t* b) {
    asm volatile(
        "mma.sync.aligned.m16n8k16.row.col.f32.f16.f16.f32 "
        "{%0,%1,%2,%3}, {%4,%5,%6,%7}, {%8,%9}, {%0,%1,%2,%3};"
        : "+f"(d[0]), "+f"(d[1]), "+f"(d[2]), "+f"(d[3])
        : "r"(a[0]), "r"(a[1]), "r"(a[2]), "r"(a[3]), "r"(b[0]), "r"(b[1]));
}

// ======================= conv GEMM (mma.sync fp16) ==========================
// CTA: M=128 (c_out) x N=128 pixels (2 rows x 64). K-chunk = 32 (one tap,
// 32 in-ch). 8 warps as 2(M) x 4(N): warp tile 64x32. 2 CTAs/SM (4 warps/SMSP).
#define PITCH 80
#define STG_B 10240
#define STAGE_SZ 20480

template <int CIN>
__device__ __forceinline__ void load_stage(
    uint32_t sb, const __half* __restrict__ w, const __half* __restrict__ x,
    int iter, int b, int h0, int tid)
{
    const int K = CIN * 9;
    int pos = iter % 9, cic = iter / 9;
    int kh = pos / 3, kw = pos - 3 * kh;
    int k0 = pos * CIN + cic * 32;
#pragma unroll
    for (int u = 0; u < 2; u++) {
        int idx = tid * 2 + u;
        int row = idx >> 2, c16 = idx & 3;
        cp16(sb + row * PITCH + c16 * 16, w + row * K + k0 + c16 * 8, 16);
    }
#pragma unroll
    for (int u = 0; u < 2; u++) {
        int idx = tid * 2 + u;
        int px = idx >> 2, c16 = idx & 3;
        int r = px >> 6, ww = px & 63;
        int y = h0 + r + kh - 1, xw = ww + kw - 1;
        bool ok = ((unsigned)y < 64u) && ((unsigned)xw < 64u);
        const __half* src = x +
            ((size_t)((b * 64 + (ok ? y : 0)) * 64 + (ok ? xw : 0))) * CIN +
            cic * 32 + c16 * 8;
        cp16(sb + STG_B + px * PITCH + c16 * 16, src, ok ? 16 : 0);
    }
}

template <int CIN, int DUAL>
__global__ __launch_bounds__(256, 2) void conv_mma_kernel(
    const __half* __restrict__ x0, const __half* __restrict__ w0,
    __half* __restrict__ y0,
    const __half* __restrict__ x1, const __half* __restrict__ w1,
    __half* __restrict__ y1p,
    float* __restrict__ part)
{
    extern __shared__ char smem[];
    const uint32_t sbase = smem_u32(smem);
    const int tid = threadIdx.x;
    const int wid = tid >> 5, lane = tid & 31;

    int bx = blockIdx.x;
    int sel = DUAL ? (bx >> 7) : 0;
    int t = DUAL ? (bx & 127) : bx;
    int b = t >> 5;
    int h0 = (t & 31) * 2;

    const __half* x = sel ? x1 : x0;
    const __half* w = sel ? w1 : w0;
    __half* yh = sel ? y1p : y0;

    const int mi = wid & 1, ni = wid >> 1;
    const int m0 = mi * 64, n0 = ni * 32;
    const int tig = lane & 3, gid = lane >> 2;
    const uint32_t frag_off = (uint32_t)((lane & 15) * PITCH + (lane >> 4) * 16);

    float acc[4][4][4];
#pragma unroll
    for (int a = 0; a < 4; a++)
#pragma unroll
        for (int j = 0; j < 4; j++)
#pragma unroll
            for (int e = 0; e < 4; e++) acc[a][j][e] = 0.f;

    constexpr int NIT = 9 * (CIN / 32);
    load_stage<CIN>(sbase, w, x, 0, b, h0, tid); CPC();
    load_stage<CIN>(sbase + STAGE_SZ, w, x, 1, b, h0, tid); CPC();

    for (int i = 0; i < NIT; i++) {
        uint32_t st = (i & 1) ? sbase + STAGE_SZ : sbase;
        if (i + 1 < NIT) asm volatile("cp.async.wait_group 1;" ::: "memory");
        else             asm volatile("cp.async.wait_group 0;" ::: "memory");
        __syncthreads();
#pragma unroll
        for (int s = 0; s < 2; s++) {
            uint32_t ah[4][4], bf[2][4];
#pragma unroll
            for (int tt = 0; tt < 4; tt++)
                ldsm_x4(ah[tt][0], ah[tt][1], ah[tt][2], ah[tt][3],
                        st + (m0 + tt * 16) * PITCH + s * 32 + frag_off);
#pragma unroll
            for (int q = 0; q < 2; q++)
                ldsm_x4(bf[q][0], bf[q][1], bf[q][2], bf[q][3],
                        st + STG_B + (n0 + q * 16) * PITCH + s * 32 + frag_off);
#pragma unroll
            for (int tt = 0; tt < 4; tt++)
#pragma unroll
                for (int q = 0; q < 2; q++) {
                    uint32_t b0[2] = { bf[q][0], bf[q][2] };
                    uint32_t b1[2] = { bf[q][1], bf[q][3] };
                    mma16816(acc[tt][q * 2 + 0], ah[tt], b0);
                    mma16816(acc[tt][q * 2 + 1], ah[tt], b1);
                }
        }
        __syncthreads();
        if (i + 2 < NIT) { load_stage<CIN>(st, w, x, i + 2, b, h0, tid); CPC(); }
    }
    __syncthreads();

    // ---- BN partials ----
    float* sst = (float*)smem;            // [8][64]
    float* ssq = (float*)(smem + 2048);
#pragma unroll
    for (int tt = 0; tt < 4; tt++) {
        float a0 = 0.f, q0 = 0.f, a1 = 0.f, q1 = 0.f;
#pragma unroll
        for (int j = 0; j < 4; j++) {
            float x0 = acc[tt][j][0], x1 = acc[tt][j][1];
            float x2 = acc[tt][j][2], x3 = acc[tt][j][3];
            a0 += x0 + x1; q0 += x0 * x0 + x1 * x1;
            a1 += x2 + x3; q1 += x2 * x2 + x3 * x3;
        }
#pragma unroll
        for (int d = 1; d < 4; d <<= 1) {
            a0 += __shfl_xor_sync(0xffffffff, a0, d);
            q0 += __shfl_xor_sync(0xffffffff, q0, d);
            a1 += __shfl_xor_sync(0xffffffff, a1, d);
            q1 += __shfl_xor_sync(0xffffffff, q1, d);
        }
        if (tig == 0) {
            int lc = tt * 16 + gid;
            sst[wid * 64 + lc] = a0;     ssq[wid * 64 + lc] = q0;
            sst[wid * 64 + lc + 8] = a1; ssq[wid * 64 + lc + 8] = q1;
        }
    }
    __syncthreads();
    if (tid < 128) {
        int c = tid, mi2 = c >> 6, lc = c & 63;
        float s = 0.f, q = 0.f;
#pragma unroll
        for (int k = 0; k < 4; k++) {
            s += sst[(2 * k + mi2) * 64 + lc];
            q += ssq[(2 * k + mi2) * 64 + lc];
        }
        part[(bx * 2 + 0) * 128 + c] = s;
        part[(bx * 2 + 1) * 128 + c] = q;
    }

    // ---- NHWC fp16 store via smem transpose (single pass, 128px x 128c) ----
    __half* sy = (__half*)(smem + 4096);  // [128][136]
    __syncthreads();
    {
        int c0 = m0 + gid;
#pragma unroll
        for (int tt = 0; tt < 4; tt++) {
            int cc = c0 + tt * 16;
#pragma unroll
            for (int j = 0; j < 4; j++) {
                int px = n0 + j * 8 + tig * 2;
                sy[px * 136 + cc]           = __float2half_rn(acc[tt][j][0]);
                sy[(px + 1) * 136 + cc]     = __float2half_rn(acc[tt][j][1]);
                sy[px * 136 + cc + 8]       = __float2half_rn(acc[tt][j][2]);
                sy[(px + 1) * 136 + cc + 8] = __float2half_rn(acc[tt][j][3]);
            }
        }
    }
    __syncthreads();
    {
        int px = tid >> 1, hp = tid & 1;
        int hrow = h0 + (px >> 6), wcol = px & 63;
        uint4* dst = (uint4*)(yh + ((size_t)((b * 64 + hrow) * 64 + wcol)) * 128 + hp * 64);
        const uint4* src = (const uint4*)(sy + px * 136 + hp * 64);
#pragma unroll
        for (int k = 0; k < 8; k++) dst[k] = src[k];
    }
}

// ---------------- prep ----------------
__global__ void prep_w_kernel(const float* __restrict__ w,
                              __half* __restrict__ wo, int CIN)
{
    int K = CIN * 9;
    int total = 128 * K;
    for (int i = blockIdx.x * blockDim.x + threadIdx.x; i < total;
         i += gridDim.x * blockDim.x) {
        int c = i / K, k = i - c * K;
        int pos = k / CIN, ci = k - pos * CIN;
        wo[i] = __float2half_rn(w[(c * CIN + ci) * 9 + pos]);
    }
}

__global__ void prep_x_kernel(const float* __restrict__ x, __half* __restrict__ xh)
{
    __shared__ float ttile[64][33];
    int bh = blockIdx.z;
    int b = bh >> 6, h = bh & 63;
    int ciT = blockIdx.y * 64, wT = blockIdx.x * 32;
    int tx = threadIdx.x, ty = threadIdx.y;
    int tid = ty * 32 + tx;
#pragma unroll
    for (int r = 0; r < 8; r++) {
        int cl = ty + r * 8;
        ttile[cl][tx] = x[((size_t)(b * 1024 + ciT + cl) * 64 + h) * 64 + wT + tx];
    }
    __syncthreads();
#pragma unroll
    for (int u = 0; u < 4; u++) {
        int idx = u * 256 + tid;
        int wloc = idx >> 5, cp = idx & 31;
        __half2 v = __floats2half2_rn(ttile[cp * 2][wloc], ttile[cp * 2 + 1][wloc]);
        size_t o2 = (((size_t)(b * 64 + h) * 64 + wT + wloc) * 1024 + ciT + cp * 2) >> 1;
        ((__half2*)xh)[o2] = v;
    }
}

// ---------------- BN reduce ----------------
__global__ void bn_reduce_kernel(const float* __restrict__ part, int nparts,
                                 const float* __restrict__ gamma,
                                 const float* __restrict__ beta,
                                 float* __restrict__ scale,
                                 float* __restrict__ shift)
{
    int c = threadIdx.x;
    float s = 0.f, q = 0.f;
    for (int i = 0; i < nparts; i++) {
        s += part[(i * 2 + 0) * 128 + c];
        q += part[(i * 2 + 1) * 128 + c];
    }
    float mean = s * (1.f / 16384.f);
    float var  = q * (1.f / 16384.f) - mean * mean;
    float sc = gamma[c] * rsqrtf(var + BN_EPS);
    scale[c] = sc;
    shift[c] = beta[c] - mean * sc;
}

// ---------------- local weighting (fused BN+ReLU) ----------------
__global__ __launch_bounds__(128) void local_weight_kernel(
    const float* __restrict__ atten,
    const __half* __restrict__ y1h,
    const float* __restrict__ sc1, const float* __restrict__ sf1,
    const __half* __restrict__ y4h,
    const float* __restrict__ sc4, const float* __restrict__ sf4,
    __half* __restrict__ o0)
{
    int bp0 = blockIdx.x * 2;
    __shared__ float att[2][81];
    for (int i = threadIdx.x; i < 162; i += 128)
        att[i / 81][i - (i / 81) * 81] = atten[(size_t)bp0 * 81 + i];
    __syncthreads();

    int px = threadIdx.x >> 6;
    int c2 = threadIdx.x & 63;
    int bp = bp0 + px;
    int b = bp >> 12, p = bp & 4095;
    int h = p >> 6, w = p & 63;

    float s1x = sc1[2 * c2], s1y = sc1[2 * c2 + 1];
    float f1x = sf1[2 * c2], f1y = sf1[2 * c2 + 1];

    float2 acc = make_float2(0.f, 0.f);
#pragma unroll
    for (int dh = 0; dh < 9; dh++) {
        int yy = h + dh - 4;
        if ((unsigned)yy >= 64u) continue;
        const __half2* row = (const __half2*)(y1h + (size_t)((b * 64 + yy) * 64) * 128) + c2;
#pragma unroll
        for (int dw = 0; dw < 9; dw++) {
            int xx = w + dw - 4;
            if ((unsigned)xx < 64u) {
                float2 v = __half22float2(row[(size_t)xx * 64]);
                float vx = fmaxf(fmaf(v.x, s1x, f1x), 0.f);
                float vy = fmaxf(fmaf(v.y, s1y, f1y), 0.f);
                float a = att[px][dh * 9 + dw];
                acc.x = fmaf(a, vx, acc.x);
                acc.y = fmaf(a, vy, acc.y);
            }
        }
    }
    float2 u = __half22float2(((const __half2*)(y4h + (size_t)bp * 128))[c2]);
    float lx = fmaxf(fmaf(u.x, sc4[2 * c2], sf4[2 * c2]), 0.f);
    float ly = fmaxf(fmaf(u.y, sc4[2 * c2 + 1], sf4[2 * c2 + 1]), 0.f);
    ((__half2*)(o0 + (size_t)bp * 128))[c2] = __floats2half2_rn(acc.x - lx, acc.y - ly);
}

// ---------------- pool + head ----------------
__global__ void pool_part_kernel(const __half* __restrict__ y5h,
                                 const float* __restrict__ sc5,
                                 const float* __restrict__ sf5,
                                 float* __restrict__ ppool)
{
    int b = blockIdx.y, chunk = blockIdx.x;
    int t = threadIdx.x;
    int c = t & 127, pp = t >> 7;
    float sc = sc5[c], sf = sf5[c];
    const __half* base = y5h + ((size_t)(b * 4096 + chunk * 256)) * 128;
    float s = 0.f;
    for (int px = pp; px < 256; px += 2) {
        float v = __half2float(base[(size_t)px * 128 + c]);
        s += fmaxf(fmaf(v, sc, sf), 0.f);
    }
    __shared__ float sh[256];
    sh[t] = s;
    __syncthreads();
    if (t < 128) ppool[(size_t)(b * 16 + chunk) * 128 + c] = sh[t] + sh[t + 128];
}

__global__ void final_kernel(const float* __restrict__ ppool,
                             const float* __restrict__ fc1w,
                             const float* __restrict__ fc1b,
                             const float* __restrict__ fc2w,
                             const float* __restrict__ fc2b,
                             float* __restrict__ out)
{
    __shared__ float pooled[4][128];
    __shared__ float hbuf[4][10];
    int t = threadIdx.x;
    for (int b = 0; b < 4; b++) {
        float s = 0.f;
        for (int i = 0; i < 16; i++) s += ppool[(size_t)(b * 16 + i) * 128 + t];
        pooled[b][t] = s * (1.f / 4096.f);
    }
    __syncthreads();
    if (t < 40) {
        int b = t / 10, j = t % 10;
        float s = fc1b[j];
        const float* wr = fc1w + j * 128;
        for (int c = 0; c < 128; c++) s = fmaf(wr[c], pooled[b][c], s);
        hbuf[b][j] = s;
    }
    __syncthreads();
    if (t < 4) {
        float s = fc2b[0];
        for (int j = 0; j < 10; j++) s = fmaf(fc2w[j], hbuf[t][j], s);
        out[t] = s;
    }
}

// ---------------- launch ----------------
extern "C" void kernel_launch(void* const* d_in, const int* in_sizes, int n_in,
                              void* d_out, int out_size)
{
    const float* low_key    = (const float*)d_in[0];
    const float* low_nonkey = (const float*)d_in[1];
    const float* atten      = (const float*)d_in[2];
    const float* w1 = (const float*)d_in[3];
    const float* g1 = (const float*)d_in[4];
    const float* b1 = (const float*)d_in[5];
    const float* w4 = (const float*)d_in[6];
    const float* g4 = (const float*)d_in[7];
    const float* b4 = (const float*)d_in[8];
    const float* w5 = (const float*)d_in[9];
    const float* g5 = (const float*)d_in[10];
    const float* b5 = (const float*)d_in[11];
    const float* fc1w = (const float*)d_in[12];
    const float* fc1b = (const float*)d_in[13];
    const float* fc2w = (const float*)d_in[14];
    const float* fc2b = (const float*)d_in[15];
    float* out = (float*)d_out;

    __half *y1h, *y4h, *y5h, *xk, *xn, *pw1, *pw4, *pw5, *o0;
    float *part, *part5, *ppool, *scale, *shift;
    cudaGetSymbolAddress((void**)&y1h, g_y1h);
    cudaGetSymbolAddress((void**)&y4h, g_y4h);
    cudaGetSymbolAddress((void**)&y5h, g_y5h);
    cudaGetSymbolAddress((void**)&xk, g_xk);
    cudaGetSymbolAddress((void**)&xn, g_xn);
    cudaGetSymbolAddress((void**)&pw1, g_w1);
    cudaGetSymbolAddress((void**)&pw4, g_w4);
    cudaGetSymbolAddress((void**)&pw5, g_w5);
    cudaGetSymbolAddress((void**)&o0, g_o0);
    cudaGetSymbolAddress((void**)&part, g_part);
    cudaGetSymbolAddress((void**)&part5, g_part5);
    cudaGetSymbolAddress((void**)&ppool, g_ppool);
    cudaGetSymbolAddress((void**)&scale, g_scale);
    cudaGetSymbolAddress((void**)&shift, g_shift);

    float* scale1 = scale + 0 * 128; float* shift1 = shift + 0 * 128;
    float* scale4 = scale + 1 * 128; float* shift4 = shift + 1 * 128;
    float* scale5 = scale + 2 * 128; float* shift5 = shift + 2 * 128;

    const int CONV_SMEM = 2 * STAGE_SZ;  // 40960
    cudaFuncSetAttribute(conv_mma_kernel<1024, 1>,
                         cudaFuncAttributeMaxDynamicSharedMemorySize, CONV_SMEM);
    cudaFuncSetAttribute(conv_mma_kernel<128, 0>,
                         cudaFuncAttributeMaxDynamicSharedMemorySize, CONV_SMEM);

    prep_w_kernel<<<512, 256>>>(w1, pw1, 1024);
    prep_w_kernel<<<512, 256>>>(w4, pw4, 1024);
    prep_w_kernel<<<64, 256>>>(w5, pw5, 128);
    {
        dim3 g(2, 16, 256), blk(32, 8);
        prep_x_kernel<<<g, blk>>>(low_key, xk);
        prep_x_kernel<<<g, blk>>>(low_nonkey, xn);
    }

    // conv1 + conv4 fused (256 CTAs, 2 CTAs/SM)
    conv_mma_kernel<1024, 1><<<256, 256, CONV_SMEM>>>(
        xk, pw1, y1h, xn, pw4, y4h, part);

    bn_reduce_kernel<<<1, 128>>>(part, 128, g1, b1, scale1, shift1);
    bn_reduce_kernel<<<1, 128>>>(part + 128 * 256, 128, g4, b4, scale4, shift4);

    local_weight_kernel<<<8192, 128>>>(atten, y1h, scale1, shift1,
                                       y4h, scale4, shift4, o0);

    conv_mma_kernel<128, 0><<<128, 256, CONV_SMEM>>>(
        o0, pw5, y5h, o0, pw5, y5h, part5);
    bn_reduce_kernel<<<1, 128>>>(part5, 128, g5, b5, scale5, shift5);

    {
        dim3 g(16, 4);
        pool_part_kernel<<<g, 256>>>(y5h, scale5, shift5, ppool);
    }
    final_kernel<<<1, 128>>>(ppool, fc1w, fc1b, fc2w, fc2b, out);
}